// round 3
// baseline (speedup 1.0000x reference)
#include <cuda_runtime.h>
#include <cstdint>

#define EMB 128
#define MAX_USERS 65536

__device__ float g_per_user[(size_t)MAX_USERS * EMB];

__device__ __forceinline__ int lower_bound_i32(const int* __restrict__ a, int n, int key) {
    int lo = 0, hi = n;
    while (lo < hi) {
        int m = (lo + hi) >> 1;
        if (__ldg(a + m) < key) lo = m + 1; else hi = m;
    }
    return lo;
}

// ---------------------------------------------------------------------------
// Kernel 1: one warp per user. Vectorized index/count loads (int4/float4)
// cut the warp-uniform scalar LDG count by 4x (LSU-issue bound workload).
// ---------------------------------------------------------------------------
__global__ void __launch_bounds__(256) per_user_kernel(
    const int* __restrict__ user_ids,
    const int* __restrict__ bitem,
    const float* __restrict__ bcnt,
    const int* __restrict__ buid,
    const float* __restrict__ user_table,
    const float* __restrict__ item_table,
    int n_users, int n_beh)
{
    const int warp = (blockIdx.x * blockDim.x + threadIdx.x) >> 5;
    const int lane = threadIdx.x & 31;
    if (warp >= n_users) return;
    const int u   = warp;
    const int col = lane * 4;

    const int s = lower_bound_i32(buid, n_beh, u);
    const int e = lower_bound_i32(buid, n_beh, u + 1);

    float4 acc = make_float4(0.f, 0.f, 0.f, 0.f);

    int j = s;
    // head peel until j is 16B-aligned (multiple of 4)
    for (; j < e && (j & 3); j++) {
        int   i0 = __ldg(bitem + j);
        float c0 = __ldg(bcnt + j);
        float4 v0 = *reinterpret_cast<const float4*>(item_table + (size_t)i0 * EMB + col);
        acc.x += c0 * v0.x; acc.y += c0 * v0.y; acc.z += c0 * v0.z; acc.w += c0 * v0.w;
    }
    // vector loop: 1 int4 + 1 float4 + 4 LDG.128 per 4 behaviors
    for (; j + 4 <= e; j += 4) {
        int4   ii = *reinterpret_cast<const int4*>(bitem + j);
        float4 cc = *reinterpret_cast<const float4*>(bcnt + j);
        float4 v0 = *reinterpret_cast<const float4*>(item_table + (size_t)ii.x * EMB + col);
        float4 v1 = *reinterpret_cast<const float4*>(item_table + (size_t)ii.y * EMB + col);
        float4 v2 = *reinterpret_cast<const float4*>(item_table + (size_t)ii.z * EMB + col);
        float4 v3 = *reinterpret_cast<const float4*>(item_table + (size_t)ii.w * EMB + col);
        acc.x += cc.x * v0.x; acc.y += cc.x * v0.y; acc.z += cc.x * v0.z; acc.w += cc.x * v0.w;
        acc.x += cc.y * v1.x; acc.y += cc.y * v1.y; acc.z += cc.y * v1.z; acc.w += cc.y * v1.w;
        acc.x += cc.z * v2.x; acc.y += cc.z * v2.y; acc.z += cc.z * v2.z; acc.w += cc.z * v2.w;
        acc.x += cc.w * v3.x; acc.y += cc.w * v3.y; acc.z += cc.w * v3.z; acc.w += cc.w * v3.w;
    }
    // tail peel
    for (; j < e; j++) {
        int   i0 = __ldg(bitem + j);
        float c0 = __ldg(bcnt + j);
        float4 v0 = *reinterpret_cast<const float4*>(item_table + (size_t)i0 * EMB + col);
        acc.x += c0 * v0.x; acc.y += c0 * v0.y; acc.z += c0 * v0.z; acc.w += c0 * v0.w;
    }

    // user embedding with padding_idx = 0
    const int uid = __ldg(user_ids + u);
    float4 outv = make_float4(0.f, 0.f, 0.f, 0.f);
    if (uid != 0) {
        float4 ue = *reinterpret_cast<const float4*>(user_table + (size_t)uid * EMB + col);
        outv.x = acc.x * ue.x;
        outv.y = acc.y * ue.y;
        outv.z = acc.z * ue.z;
        outv.w = acc.w * ue.w;
    }
    *reinterpret_cast<float4*>(g_per_user + (size_t)u * EMB + col) = outv;
}

// ---------------------------------------------------------------------------
// Kernel 2: one 512-thread CTA per group. Each column is handled by 4 threads
// over disjoint strided user partitions, then a fixed-order smem combine
// (deterministic).
// ---------------------------------------------------------------------------
__global__ void __launch_bounds__(512) group_sum_kernel(
    const int* __restrict__ ugid,
    float* __restrict__ out,
    int n_users, int num_groups)
{
    const int g    = blockIdx.x;
    const int t    = threadIdx.x & (EMB - 1);  // column 0..127
    const int part = threadIdx.x >> 7;         // partition 0..3

    __shared__ float s_part[4 * EMB];

    const int s = lower_bound_i32(ugid, n_users, g);
    const int e = lower_bound_i32(ugid, n_users, g + 1);

    float acc = 0.f;
    for (int u = s + part; u < e; u += 4) {
        acc += g_per_user[(size_t)u * EMB + t];
    }
    s_part[part * EMB + t] = acc;
    __syncthreads();

    if (threadIdx.x < EMB) {
        float r = s_part[t] + s_part[EMB + t] + s_part[2 * EMB + t] + s_part[3 * EMB + t];
        out[(size_t)g * EMB + t] = r;
    }
}

extern "C" void kernel_launch(void* const* d_in, const int* in_sizes, int n_in,
                              void* d_out, int out_size)
{
    const int*   user_ids   = (const int*)  d_in[0];
    const int*   ugid       = (const int*)  d_in[1];
    const int*   bitem      = (const int*)  d_in[2];
    const float* bcnt       = (const float*)d_in[3];
    const int*   buid       = (const int*)  d_in[4];
    const float* user_table = (const float*)d_in[5];
    const float* item_table = (const float*)d_in[6];

    const int n_users    = in_sizes[0];
    const int n_beh      = in_sizes[2];
    const int num_groups = out_size / EMB;

    float* out = (float*)d_out;

    {
        const int warps_per_block = 8;
        const int threads = warps_per_block * 32;
        const int blocks = (n_users + warps_per_block - 1) / warps_per_block;
        per_user_kernel<<<blocks, threads>>>(user_ids, bitem, bcnt, buid,
                                             user_table, item_table,
                                             n_users, n_beh);
    }

    group_sum_kernel<<<num_groups, 512>>>(ugid, out, n_users, num_groups);
}

// round 4
// speedup vs baseline: 1.1963x; 1.1963x over previous
#include <cuda_runtime.h>
#include <cstdint>

#define EMB 128

__device__ __forceinline__ int lower_bound_i32(const int* __restrict__ a, int n, int key) {
    int lo = 0, hi = n;
    while (lo < hi) {
        int m = (lo + hi) >> 1;
        if (__ldg(a + m) < key) lo = m + 1; else hi = m;
    }
    return lo;
}

__global__ void __launch_bounds__(256) zero_out_kernel(float* __restrict__ out, int n) {
    int i = blockIdx.x * blockDim.x + threadIdx.x;
    if (i < n) out[i] = 0.f;
}

// ---------------------------------------------------------------------------
// One warp per user. Gather item rows over the user's (sorted-contiguous)
// behavior segment with 4 independent accumulators for MLP, multiply by the
// user embedding (padding_idx=0), and atomically accumulate straight into the
// group output row. No scratch, no second pass.
// ---------------------------------------------------------------------------
__global__ void __launch_bounds__(256) per_user_kernel(
    const int* __restrict__ user_ids,
    const int* __restrict__ ugid,
    const int* __restrict__ bitem,
    const float* __restrict__ bcnt,
    const int* __restrict__ buid,
    const float* __restrict__ user_table,
    const float* __restrict__ item_table,
    float* __restrict__ out,
    int n_users, int n_beh)
{
    const int warp = (blockIdx.x * blockDim.x + threadIdx.x) >> 5;
    const int lane = threadIdx.x & 31;
    if (warp >= n_users) return;
    const int u   = warp;
    const int col = lane * 4;

    // user embedding gate first: if uid==0 the result contributes nothing.
    const int uid = __ldg(user_ids + u);
    if (uid == 0) return;

    const int s = lower_bound_i32(buid, n_beh, u);
    const int e = lower_bound_i32(buid, n_beh, u + 1);

    float4 a0 = make_float4(0.f, 0.f, 0.f, 0.f);
    float4 a1 = make_float4(0.f, 0.f, 0.f, 0.f);
    float4 a2 = make_float4(0.f, 0.f, 0.f, 0.f);
    float4 a3 = make_float4(0.f, 0.f, 0.f, 0.f);

    int j = s;
    for (; j + 3 < e; j += 4) {
        int   i0 = __ldg(bitem + j + 0);
        int   i1 = __ldg(bitem + j + 1);
        int   i2 = __ldg(bitem + j + 2);
        int   i3 = __ldg(bitem + j + 3);
        float c0 = __ldg(bcnt + j + 0);
        float c1 = __ldg(bcnt + j + 1);
        float c2 = __ldg(bcnt + j + 2);
        float c3 = __ldg(bcnt + j + 3);
        float4 v0 = *reinterpret_cast<const float4*>(item_table + (size_t)i0 * EMB + col);
        float4 v1 = *reinterpret_cast<const float4*>(item_table + (size_t)i1 * EMB + col);
        float4 v2 = *reinterpret_cast<const float4*>(item_table + (size_t)i2 * EMB + col);
        float4 v3 = *reinterpret_cast<const float4*>(item_table + (size_t)i3 * EMB + col);
        a0.x += c0 * v0.x; a0.y += c0 * v0.y; a0.z += c0 * v0.z; a0.w += c0 * v0.w;
        a1.x += c1 * v1.x; a1.y += c1 * v1.y; a1.z += c1 * v1.z; a1.w += c1 * v1.w;
        a2.x += c2 * v2.x; a2.y += c2 * v2.y; a2.z += c2 * v2.z; a2.w += c2 * v2.w;
        a3.x += c3 * v3.x; a3.y += c3 * v3.y; a3.z += c3 * v3.z; a3.w += c3 * v3.w;
    }
    for (; j < e; j++) {
        int   i0 = __ldg(bitem + j);
        float c0 = __ldg(bcnt + j);
        float4 v0 = *reinterpret_cast<const float4*>(item_table + (size_t)i0 * EMB + col);
        a0.x += c0 * v0.x; a0.y += c0 * v0.y; a0.z += c0 * v0.z; a0.w += c0 * v0.w;
    }

    // fixed-order combine
    float4 acc;
    acc.x = (a0.x + a1.x) + (a2.x + a3.x);
    acc.y = (a0.y + a1.y) + (a2.y + a3.y);
    acc.z = (a0.z + a1.z) + (a2.z + a3.z);
    acc.w = (a0.w + a1.w) + (a2.w + a3.w);

    float4 ue = *reinterpret_cast<const float4*>(user_table + (size_t)uid * EMB + col);

    const int g = __ldg(ugid + u);
    float* dst = out + (size_t)g * EMB + col;
    atomicAdd(dst + 0, acc.x * ue.x);
    atomicAdd(dst + 1, acc.y * ue.y);
    atomicAdd(dst + 2, acc.z * ue.z);
    atomicAdd(dst + 3, acc.w * ue.w);
}

extern "C" void kernel_launch(void* const* d_in, const int* in_sizes, int n_in,
                              void* d_out, int out_size)
{
    const int*   user_ids   = (const int*)  d_in[0];
    const int*   ugid       = (const int*)  d_in[1];
    const int*   bitem      = (const int*)  d_in[2];
    const float* bcnt       = (const float*)d_in[3];
    const int*   buid       = (const int*)  d_in[4];
    const float* user_table = (const float*)d_in[5];
    const float* item_table = (const float*)d_in[6];

    const int n_users = in_sizes[0];
    const int n_beh   = in_sizes[2];

    float* out = (float*)d_out;

    zero_out_kernel<<<(out_size + 255) / 256, 256>>>(out, out_size);

    const int warps_per_block = 8;
    const int threads = warps_per_block * 32;
    const int blocks = (n_users + warps_per_block - 1) / warps_per_block;
    per_user_kernel<<<blocks, threads>>>(user_ids, ugid, bitem, bcnt, buid,
                                         user_table, item_table, out,
                                         n_users, n_beh);
}

// round 5
// speedup vs baseline: 1.5835x; 1.3237x over previous
#include <cuda_runtime.h>
#include <cstdint>

#define EMB 128
#define MAX_USERS 65536
#define MAX_GROUPS 4096

// scratch (allocation-free rule: __device__ globals)
__device__ float g_per_user[(size_t)MAX_USERS * EMB];   // 32 MB
__device__ int   g_u_off[MAX_USERS + 1];
__device__ int   g_g_off[MAX_GROUPS + 1];

__device__ __forceinline__ int lower_bound_i32(const int* __restrict__ a, int n, int key) {
    int lo = 0, hi = n;
    while (lo < hi) {
        int m = (lo + hi) >> 1;
        if (__ldg(a + m) < key) lo = m + 1; else hi = m;
    }
    return lo;
}

// Prologue 1: behavior-segment offsets per user (thread-parallel searches).
__global__ void __launch_bounds__(256) user_off_kernel(
    const int* __restrict__ buid, int n_beh, int n_users)
{
    int u = blockIdx.x * blockDim.x + threadIdx.x;
    if (u <= n_users) g_u_off[u] = lower_bound_i32(buid, n_beh, u);
}

// Prologue 2: user-segment offsets per group.
__global__ void __launch_bounds__(256) group_off_kernel(
    const int* __restrict__ ugid, int n_users, int num_groups)
{
    int g = blockIdx.x * blockDim.x + threadIdx.x;
    if (g <= num_groups) g_g_off[g] = lower_bound_i32(ugid, n_users, g);
}

// ---------------------------------------------------------------------------
// Kernel 1: one warp per user. Offsets precomputed. Unroll x4, 2 accumulators
// (register-lean -> high occupancy). Streaming store of per_user scratch.
// ---------------------------------------------------------------------------
__global__ void __launch_bounds__(256) per_user_kernel(
    const int* __restrict__ user_ids,
    const int* __restrict__ bitem,
    const float* __restrict__ bcnt,
    const float* __restrict__ user_table,
    const float* __restrict__ item_table,
    int n_users)
{
    const int warp = (blockIdx.x * blockDim.x + threadIdx.x) >> 5;
    const int lane = threadIdx.x & 31;
    if (warp >= n_users) return;
    const int u   = warp;
    const int col = lane * 4;

    float4* dst = reinterpret_cast<float4*>(g_per_user + (size_t)u * EMB + col);

    const int uid = __ldg(user_ids + u);
    if (uid == 0) {
        __stcs(dst, make_float4(0.f, 0.f, 0.f, 0.f));
        return;
    }

    const int s = g_u_off[u];
    const int e = g_u_off[u + 1];

    float4 a0 = make_float4(0.f, 0.f, 0.f, 0.f);
    float4 a1 = make_float4(0.f, 0.f, 0.f, 0.f);

    int j = s;
    for (; j + 3 < e; j += 4) {
        int   i0 = __ldg(bitem + j + 0);
        int   i1 = __ldg(bitem + j + 1);
        int   i2 = __ldg(bitem + j + 2);
        int   i3 = __ldg(bitem + j + 3);
        float c0 = __ldg(bcnt + j + 0);
        float c1 = __ldg(bcnt + j + 1);
        float c2 = __ldg(bcnt + j + 2);
        float c3 = __ldg(bcnt + j + 3);
        float4 v0 = *reinterpret_cast<const float4*>(item_table + (size_t)i0 * EMB + col);
        float4 v1 = *reinterpret_cast<const float4*>(item_table + (size_t)i1 * EMB + col);
        float4 v2 = *reinterpret_cast<const float4*>(item_table + (size_t)i2 * EMB + col);
        float4 v3 = *reinterpret_cast<const float4*>(item_table + (size_t)i3 * EMB + col);
        a0.x += c0 * v0.x; a0.y += c0 * v0.y; a0.z += c0 * v0.z; a0.w += c0 * v0.w;
        a1.x += c1 * v1.x; a1.y += c1 * v1.y; a1.z += c1 * v1.z; a1.w += c1 * v1.w;
        a0.x += c2 * v2.x; a0.y += c2 * v2.y; a0.z += c2 * v2.z; a0.w += c2 * v2.w;
        a1.x += c3 * v3.x; a1.y += c3 * v3.y; a1.z += c3 * v3.z; a1.w += c3 * v3.w;
    }
    for (; j < e; j++) {
        int   i0 = __ldg(bitem + j);
        float c0 = __ldg(bcnt + j);
        float4 v0 = *reinterpret_cast<const float4*>(item_table + (size_t)i0 * EMB + col);
        a0.x += c0 * v0.x; a0.y += c0 * v0.y; a0.z += c0 * v0.z; a0.w += c0 * v0.w;
    }

    float4 ue = *reinterpret_cast<const float4*>(user_table + (size_t)uid * EMB + col);
    float4 outv;
    outv.x = (a0.x + a1.x) * ue.x;
    outv.y = (a0.y + a1.y) * ue.y;
    outv.z = (a0.z + a1.z) * ue.z;
    outv.w = (a0.w + a1.w) * ue.w;
    __stcs(dst, outv);
}

// ---------------------------------------------------------------------------
// Kernel 2: one 128-thread CTA per group, offsets precomputed, unroll x4
// streaming loads, fixed summation order (deterministic).
// ---------------------------------------------------------------------------
__global__ void __launch_bounds__(128) group_sum_kernel(
    float* __restrict__ out, int num_groups)
{
    const int g = blockIdx.x;
    const int t = threadIdx.x;
    if (g >= num_groups) return;

    const int s = g_g_off[g];
    const int e = g_g_off[g + 1];

    float acc0 = 0.f, acc1 = 0.f, acc2 = 0.f, acc3 = 0.f;
    int u = s;
    for (; u + 3 < e; u += 4) {
        acc0 += __ldcs(g_per_user + (size_t)(u + 0) * EMB + t);
        acc1 += __ldcs(g_per_user + (size_t)(u + 1) * EMB + t);
        acc2 += __ldcs(g_per_user + (size_t)(u + 2) * EMB + t);
        acc3 += __ldcs(g_per_user + (size_t)(u + 3) * EMB + t);
    }
    for (; u < e; u++) {
        acc0 += __ldcs(g_per_user + (size_t)u * EMB + t);
    }
    out[(size_t)g * EMB + t] = (acc0 + acc1) + (acc2 + acc3);
}

extern "C" void kernel_launch(void* const* d_in, const int* in_sizes, int n_in,
                              void* d_out, int out_size)
{
    const int*   user_ids   = (const int*)  d_in[0];
    const int*   ugid       = (const int*)  d_in[1];
    const int*   bitem      = (const int*)  d_in[2];
    const float* bcnt       = (const float*)d_in[3];
    const int*   buid       = (const int*)  d_in[4];
    const float* user_table = (const float*)d_in[5];
    const float* item_table = (const float*)d_in[6];

    const int n_users    = in_sizes[0];
    const int n_beh      = in_sizes[2];
    const int num_groups = out_size / EMB;

    float* out = (float*)d_out;

    user_off_kernel<<<(n_users + 256) / 256, 256>>>(buid, n_beh, n_users);
    group_off_kernel<<<(num_groups + 256) / 256, 256>>>(ugid, n_users, num_groups);

    {
        const int warps_per_block = 8;
        const int threads = warps_per_block * 32;
        const int blocks = (n_users + warps_per_block - 1) / warps_per_block;
        per_user_kernel<<<blocks, threads>>>(user_ids, bitem, bcnt,
                                             user_table, item_table, n_users);
    }

    group_sum_kernel<<<num_groups, 128>>>(out, num_groups);
}